// round 12
// baseline (speedup 1.0000x reference)
#include <cuda_runtime.h>
#include <cuda_fp16.h>
#include <cstdint>

#define CIN 3
#define NY  31
#define POS 961
#define POq 48

// ---- smem layout (bytes) ----
#define SBIAS 0          // 48 floats
#define RAW0  1024       // raw fp32 weight ring: 3 slots x 6144B (1536 floats each)
#define RAW1  7168
#define RAW2  13312
#define A0    19456      // A tile: 128 rows x 64B (32 halves = K32), swizzled, fp16
#define A1    27648
#define B0    35840      // B tile: 32 rows x 128B (48 halves used), swizzled, fp16
#define B1    39936
#define SMEM_BYTES 44032

// A-tile swizzle: row is 64B = 4 chunks of 16B. 2-bit XOR (kc in 0..3). Validated R6-R9.
#define ASWZ(row, kc) ((uint32_t)(((kc) ^ (((row) >> 1) & 3u) ^ (((row) >> 3) & 3u))))

__device__ __forceinline__ uint32_t smem_u32(const void* p) {
    uint32_t a;
    asm("{ .reg .u64 t; cvta.to.shared.u64 t, %1; cvt.u32.u64 %0, t; }" : "=r"(a) : "l"(p));
    return a;
}
__device__ __forceinline__ void cp_async16(uint32_t dst, const void* src) {
    asm volatile("cp.async.ca.shared.global [%0], [%1], 16;" :: "r"(dst), "l"(src) : "memory");
}
__device__ __forceinline__ void cp_commit() {
    asm volatile("cp.async.commit_group;" ::: "memory");
}
__device__ __forceinline__ void cp_wait1() {
    asm volatile("cp.async.wait_group 1;" ::: "memory");
}
__device__ __forceinline__ void cp_wait0() {
    asm volatile("cp.async.wait_group 0;" ::: "memory");
}
__device__ __forceinline__ void ldsm_x4(uint32_t& r0, uint32_t& r1, uint32_t& r2, uint32_t& r3,
                                        uint32_t a) {
    asm volatile("ldmatrix.sync.aligned.m8n8.x4.shared.b16 {%0,%1,%2,%3}, [%4];"
                 : "=r"(r0), "=r"(r1), "=r"(r2), "=r"(r3) : "r"(a));
}
__device__ __forceinline__ void ldsm_x4t(uint32_t& r0, uint32_t& r1, uint32_t& r2, uint32_t& r3,
                                         uint32_t a) {
    asm volatile("ldmatrix.sync.aligned.m8n8.x4.trans.shared.b16 {%0,%1,%2,%3}, [%4];"
                 : "=r"(r0), "=r"(r1), "=r"(r2), "=r"(r3) : "r"(a));
}
__device__ __forceinline__ void mma16816(float& d0, float& d1, float& d2, float& d3,
                                         uint32_t a0, uint32_t a1, uint32_t a2, uint32_t a3,
                                         uint32_t b0, uint32_t b1) {
    asm volatile("mma.sync.aligned.m16n8k16.row.col.f32.f16.f16.f32 "
                 "{%0,%1,%2,%3}, {%4,%5,%6,%7}, {%8,%9}, {%0,%1,%2,%3};"
                 : "+f"(d0), "+f"(d1), "+f"(d2), "+f"(d3)
                 : "r"(a0), "r"(a1), "r"(a2), "r"(a3), "r"(b0), "r"(b1));
}
__device__ __forceinline__ uint32_t pack_hi(float v0, float v1) {
    __half h0 = __float2half_rn(v0), h1 = __float2half_rn(v1);
    return (uint32_t)__half_as_ushort(h0) | ((uint32_t)__half_as_ushort(h1) << 16);
}
__device__ __forceinline__ void sts64(uint32_t a, uint32_t v0, uint32_t v1) {
    asm volatile("st.shared.v2.b32 [%0], {%1,%2};" :: "r"(a), "r"(v0), "r"(v1) : "memory");
}
__device__ __forceinline__ void sts32(uint32_t a, uint32_t v) {
    asm volatile("st.shared.b32 [%0], %1;" :: "r"(a), "r"(v) : "memory");
}

extern __shared__ char smem[];

__global__ void __launch_bounds__(128, 4)
ttn_conv_hmma_kernel(const float* __restrict__ x,
                     const float* __restrict__ w,
                     const float* __restrict__ bias,
                     float* __restrict__ out)
{
    const int pos  = blockIdx.x;
    const int xx   = pos / NY;
    const int yy   = pos - xx * NY;
    const int tid  = threadIdx.x;
    const int lane = tid & 31;
    const int wid  = tid >> 5;
    const uint32_t sb = smem_u32(smem);
    float* sbias = (float*)(smem + SBIAS);

    if (tid < POq) {
        int p = tid / 6, o = tid - p * 6;
        sbias[tid] = bias[((p * 31 + xx) * 31 + yy) * 6 + o];
    }

    const int bp  = tid >> 4;     // p block (0..7) for weight loads
    const int t16 = tid & 15;

    float D[48];
    #pragma unroll
    for (int i = 0; i < 48; i++) D[i] = 0.f;

    float xv[16];                 // current c precursors (a,b,c,d x 4)

    const uint32_t raw_off[3] = { RAW0, RAW1, RAW2 };

    auto load_x = [&](int c) {
        const float* xp = x + ((size_t)tid * CIN + c) * 4096 + xx * 32 + yy;
        #pragma unroll
        for (int i = 0; i < 4; i++) {
            xv[i]      = xp[i * 1024];
            xv[4 + i]  = xp[i * 1024 + 32];
            xv[8 + i]  = xp[i * 1024 + 1];
            xv[12 + i] = xp[i * 1024 + 33];
        }
    };
    // issue cp.async for raw weights of stage st into ring slot st%3, commit as one group
    auto cp_w = [&](int st) {
        int c = st >> 3, s = st & 7;
        const float* gw = w + ((size_t)(c * 8 + bp) * POS + pos) * 1536 + s * 192;
        const uint32_t dst = sb + raw_off[st % 3] + (uint32_t)(bp * 768);
        #pragma unroll
        for (int r = 0; r < 3; r++)
            cp_async16(dst + (uint32_t)((t16 + 16 * r) * 16), gw + (t16 + 16 * r) * 4);
        cp_commit();
    };
    // convert raw[st%3] -> fp16 A/B tiles buf[st&1]   (K32 data path, validated R8)
    auto stage = [&](int st) {
        const int s   = st & 7;
        const int buf = st & 1;
        const uint32_t ah = sb + (buf ? A1 : A0);
        const uint32_t bh = sb + (buf ? B1 : B0);

        // A (fp16): row = tid, k-local 0..31 = ab[2s+h] * cd[kl]
        const uint32_t row = (uint32_t)tid;
        #pragma unroll
        for (int h = 0; h < 2; h++) {
            const int t2 = s * 2 + h;
            const float abv = xv[t2 >> 2] * xv[4 + (t2 & 3)];
            #pragma unroll
            for (int g4 = 0; g4 < 4; g4++) {
                const float t0 = abv * xv[8 + g4];
                float v0 = t0 * xv[12 + 0];
                float v1 = t0 * xv[12 + 1];
                float v2 = t0 * xv[12 + 2];
                float v3 = t0 * xv[12 + 3];
                uint32_t kc  = (uint32_t)(h * 2 + (g4 >> 1));
                uint32_t off = row * 64u + 16u * ASWZ(row, kc) + (uint32_t)(g4 & 1) * 8u;
                sts64(ah + off, pack_hi(v0, v1), pack_hi(v2, v3));
            }
        }
        // B (fp16): read own raw floats, paired o-values -> sts32
        const float4* rp = (const float4*)(smem + raw_off[st % 3] + bp * 768);
        #pragma unroll
        for (int r = 0; r < 3; r++) {
            const float4 f = rp[t16 + 16 * r];
            const float* fp = &f.x;
            #pragma unroll
            for (int up = 0; up < 2; up++) {
                int e0 = t16 * 4 + up * 2 + r * 64;   // even; e0%6 in {0,2,4} -> same-k pair
                int k  = e0 / 6, o = e0 - 6 * k;      // k 0..31
                uint32_t n   = (uint32_t)(bp * 6 + o);
                uint32_t off = (uint32_t)k * 128u + 16u * ((n >> 3) ^ ((uint32_t)k & 7u))
                             + (n & 7u) * 2u;
                sts32(bh + off, pack_hi(fp[up * 2], fp[up * 2 + 1]));
            }
        }
    };
    auto compute = [&](int buf) {
        const uint32_t ah = sb + (buf ? A1 : A0);
        const uint32_t bh = sb + (buf ? B1 : B0);
        #pragma unroll
        for (int s16 = 0; s16 < 2; s16++) {
            uint32_t Bh[12];
            uint32_t krow = (uint32_t)(s16 * 16 + ((lane >> 3) & 1) * 8 + (lane & 7));
            #pragma unroll
            for (int ntp = 0; ntp < 3; ntp++) {
                uint32_t n    = (uint32_t)((ntp * 2 + (lane >> 4)) * 8);
                uint32_t boff = krow * 128u + 16u * ((n >> 3) ^ (krow & 7u));
                ldsm_x4t(Bh[ntp * 4], Bh[ntp * 4 + 1], Bh[ntp * 4 + 2], Bh[ntp * 4 + 3], bh + boff);
            }
            #pragma unroll
            for (int mt = 0; mt < 2; mt++) {
                uint32_t row = (uint32_t)(wid * 32 + mt * 16 + (lane & 15));
                uint32_t kc  = (uint32_t)(s16 * 2 + (lane >> 4));
                uint32_t aoff = row * 64u + 16u * ASWZ(row, kc);
                uint32_t Ah[4];
                ldsm_x4(Ah[0], Ah[1], Ah[2], Ah[3], ah + aoff);
                #pragma unroll
                for (int nt = 0; nt < 6; nt++) {
                    float* d = D + (mt * 6 + nt) * 4;
                    uint32_t b0 = (nt & 1) ? Bh[(nt >> 1) * 4 + 2] : Bh[(nt >> 1) * 4 + 0];
                    uint32_t b1 = (nt & 1) ? Bh[(nt >> 1) * 4 + 3] : Bh[(nt >> 1) * 4 + 1];
                    mma16816(d[0], d[1], d[2], d[3], Ah[0], Ah[1], Ah[2], Ah[3], b0, b1);
                }
            }
        }
    };

    // ---- prologue: ring 2 deep, convert stage 0 ----
    cp_w(0);
    cp_w(1);
    load_x(0);
    cp_wait1();          // stage-0 raw ready (own-thread data)
    stage(0);
    __syncthreads();

    // ---- pipeline: 24 stages of K=32 ----
    #pragma unroll 1
    for (int st = 0; st < 24; st++) {
        if (st + 2 < 24) cp_w(st + 2);
        if (st == 7) load_x(1);          // consumed first by stage(8) below
        if (st == 15) load_x(2);
        if (st < 23) {
            if (st + 2 < 24) cp_wait1(); else cp_wait0();
            stage(st + 1);               // convert raw -> fp16 buf (other buffer)
        }
        compute(st & 1);
        __syncthreads();
    }

    // ---- epilogue ----
    #pragma unroll
    for (int mt = 0; mt < 2; mt++)
        #pragma unroll
        for (int nt = 0; nt < 6; nt++)
            #pragma unroll
            for (int r = 0; r < 4; r++) {
                int row = wid * 32 + mt * 16 + (lane >> 2) + ((r >= 2) ? 8 : 0);
                int q   = nt * 8 + (lane & 3) * 2 + (r & 1);
                out[((size_t)row * POq + q) * POS + pos] = D[(mt * 6 + nt) * 4 + r] + sbias[q];
            }
}

extern "C" void kernel_launch(void* const* d_in, const int* in_sizes, int n_in,
                              void* d_out, int out_size) {
    const float* x    = (const float*)d_in[0];
    const float* w    = (const float*)d_in[1];
    const float* bias = (const float*)d_in[2];
    float* out        = (float*)d_out;
    (void)in_sizes; (void)n_in; (void)out_size;

    cudaFuncSetAttribute(ttn_conv_hmma_kernel,
                         cudaFuncAttributeMaxDynamicSharedMemorySize, SMEM_BYTES);
    ttn_conv_hmma_kernel<<<POS, 128, SMEM_BYTES>>>(x, w, bias, out);
}

// round 13
// speedup vs baseline: 1.3640x; 1.3640x over previous
#include <cuda_runtime.h>
#include <cuda_fp16.h>
#include <cstdint>

#define CIN 3
#define NY  31
#define POS 961
#define POq 48

// ---- smem layout (bytes) ----
#define SBIAS 0          // 48 floats
#define A0    1024       // A tile: 64 rows x 128B (64 halves = K64), swizzled, fp16
#define A1    9216
#define B0    17408      // B tile: 64 k-rows x 128B (48 halves used), swizzled, fp16
#define B1    25600
#define SMEM_BYTES 33792

// A swizzle: row = 128B = 8 chunks of 16B, kc in 0..7. Validated R10.
#define ASWZ8(row, kc) ((uint32_t)(((kc) ^ ((row) & 7u) ^ (((row) >> 3) & 7u))))

__device__ __forceinline__ uint32_t smem_u32(const void* p) {
    uint32_t a;
    asm("{ .reg .u64 t; cvta.to.shared.u64 t, %1; cvt.u32.u64 %0, t; }" : "=r"(a) : "l"(p));
    return a;
}
__device__ __forceinline__ void ldsm_x4(uint32_t& r0, uint32_t& r1, uint32_t& r2, uint32_t& r3,
                                        uint32_t a) {
    asm volatile("ldmatrix.sync.aligned.m8n8.x4.shared.b16 {%0,%1,%2,%3}, [%4];"
                 : "=r"(r0), "=r"(r1), "=r"(r2), "=r"(r3) : "r"(a));
}
__device__ __forceinline__ void ldsm_x4t(uint32_t& r0, uint32_t& r1, uint32_t& r2, uint32_t& r3,
                                         uint32_t a) {
    asm volatile("ldmatrix.sync.aligned.m8n8.x4.trans.shared.b16 {%0,%1,%2,%3}, [%4];"
                 : "=r"(r0), "=r"(r1), "=r"(r2), "=r"(r3) : "r"(a));
}
__device__ __forceinline__ void mma16816(float& d0, float& d1, float& d2, float& d3,
                                         uint32_t a0, uint32_t a1, uint32_t a2, uint32_t a3,
                                         uint32_t b0, uint32_t b1) {
    asm volatile("mma.sync.aligned.m16n8k16.row.col.f32.f16.f16.f32 "
                 "{%0,%1,%2,%3}, {%4,%5,%6,%7}, {%8,%9}, {%0,%1,%2,%3};"
                 : "+f"(d0), "+f"(d1), "+f"(d2), "+f"(d3)
                 : "r"(a0), "r"(a1), "r"(a2), "r"(a3), "r"(b0), "r"(b1));
}
__device__ __forceinline__ uint32_t pack_hi(float v0, float v1) {
    __half h0 = __float2half_rn(v0), h1 = __float2half_rn(v1);
    return (uint32_t)__half_as_ushort(h0) | ((uint32_t)__half_as_ushort(h1) << 16);
}
__device__ __forceinline__ void sts64(uint32_t a, uint32_t v0, uint32_t v1) {
    asm volatile("st.shared.v2.b32 [%0], {%1,%2};" :: "r"(a), "r"(v0), "r"(v1) : "memory");
}
__device__ __forceinline__ void sts32(uint32_t a, uint32_t v) {
    asm volatile("st.shared.b32 [%0], %1;" :: "r"(a), "r"(v) : "memory");
}

extern __shared__ char smem[];

__global__ void __launch_bounds__(128, 5)
ttn_conv_hmma_kernel(const float* __restrict__ x,
                     const float* __restrict__ w,
                     const float* __restrict__ bias,
                     float* __restrict__ out)
{
    const int pos   = blockIdx.x >> 1;     // position; 2 CTAs per position
    const int mhalf = blockIdx.x & 1;      // which 64-row half of M=128
    const int xx    = pos / NY;
    const int yy    = pos - xx * NY;
    const int tid   = threadIdx.x;
    const int lane  = tid & 31;
    const int wid   = tid >> 5;
    const int base  = mhalf * 64;          // global row offset
    const int rloc  = tid & 63;            // local A row this thread stages
    const int kh    = tid >> 6;            // which 32-wide k-half this thread stages
    const uint32_t sb = smem_u32(smem);
    float* sbias = (float*)(smem + SBIAS);

    if (tid < POq) {
        int p = tid / 6, o = tid - p * 6;
        sbias[tid] = bias[((p * 31 + xx) * 31 + yy) * 6 + o];
    }

    const int bp  = tid >> 4;     // p block (0..7) for weight loads
    const int t16 = tid & 15;

    float D[24];
    #pragma unroll
    for (int i = 0; i < 24; i++) D[i] = 0.f;

    float xv[16];                 // current c precursors (a,b,c,d x 4) for row base+rloc
    float4 fb[6];                 // weight prefetch (384 floats / 16 thr / p-block)

    auto load_x = [&](int c) {
        const float* xp = x + ((size_t)(base + rloc) * CIN + c) * 4096 + xx * 32 + yy;
        #pragma unroll
        for (int i = 0; i < 4; i++) {
            xv[i]      = xp[i * 1024];
            xv[4 + i]  = xp[i * 1024 + 32];
            xv[8 + i]  = xp[i * 1024 + 1];
            xv[12 + i] = xp[i * 1024 + 33];
        }
    };
    auto ldg_w = [&](int st) {      // stage st covers 384 floats per p-block
        int c = st >> 2;
        const float* gw = w + ((size_t)(c * 8 + bp) * POS + pos) * 1536 + (st & 3) * 384;
        #pragma unroll
        for (int r = 0; r < 6; r++) fb[r] = ((const float4*)gw)[t16 + 16 * r];
    };
    auto stage = [&](int st) {
        const int sl  = st & 3;       // stage-local within c
        const int buf = st & 1;
        const uint32_t ah = sb + (buf ? A1 : A0);
        const uint32_t bh = sb + (buf ? B1 : B0);

        // A: row = rloc, this thread covers k-local kh*32..kh*32+31
        const uint32_t row = (uint32_t)rloc;
        #pragma unroll
        for (int hh = 0; hh < 2; hh++) {
            const int h  = kh * 2 + hh;            // 0..3
            const int t2 = sl * 4 + h;
            const float abv = xv[t2 >> 2] * xv[4 + (t2 & 3)];
            #pragma unroll
            for (int g4 = 0; g4 < 4; g4++) {
                const float t0 = abv * xv[8 + g4];
                float v0 = t0 * xv[12 + 0];
                float v1 = t0 * xv[12 + 1];
                float v2 = t0 * xv[12 + 2];
                float v3 = t0 * xv[12 + 3];
                uint32_t kc  = (uint32_t)(h * 2 + (g4 >> 1));
                uint32_t off = row * 128u + 16u * ASWZ8(row, kc) + (uint32_t)(g4 & 1) * 8u;
                sts64(ah + off, pack_hi(v0, v1), pack_hi(v2, v3));
            }
        }
        // B: fp16, paired o-values -> sts32 (identical to validated R10 path)
        #pragma unroll
        for (int r = 0; r < 6; r++) {
            const float* fp = &fb[r].x;
            #pragma unroll
            for (int up = 0; up < 2; up++) {
                int e0 = t16 * 4 + up * 2 + r * 64;   // even; e0%6 in {0,2,4} -> same-k pair
                int k  = e0 / 6, o = e0 - 6 * k;      // k 0..63
                uint32_t n   = (uint32_t)(bp * 6 + o);
                uint32_t off = (uint32_t)k * 128u + 16u * ((n >> 3) ^ ((uint32_t)k & 7u))
                             + (n & 7u) * 2u;
                sts32(bh + off, pack_hi(fp[up * 2], fp[up * 2 + 1]));
            }
        }
    };
    auto compute = [&](int buf) {
        const uint32_t ah = sb + (buf ? A1 : A0);
        const uint32_t bh = sb + (buf ? B1 : B0);
        #pragma unroll
        for (int s16 = 0; s16 < 4; s16++) {
            uint32_t Bh[12];
            uint32_t krow = (uint32_t)(s16 * 16 + ((lane >> 3) & 1) * 8 + (lane & 7));
            #pragma unroll
            for (int ntp = 0; ntp < 3; ntp++) {
                uint32_t n    = (uint32_t)((ntp * 2 + (lane >> 4)) * 8);
                uint32_t boff = krow * 128u + 16u * ((n >> 3) ^ (krow & 7u));
                ldsm_x4t(Bh[ntp * 4], Bh[ntp * 4 + 1], Bh[ntp * 4 + 2], Bh[ntp * 4 + 3], bh + boff);
            }
            // A frags: this warp's single 16-row tile (rows wid*16..+15 local)
            uint32_t row = (uint32_t)(wid * 16 + (lane & 15));
            uint32_t kc  = (uint32_t)(s16 * 2 + (lane >> 4));
            uint32_t aoff = row * 128u + 16u * ASWZ8(row, kc);
            uint32_t Ah[4];
            ldsm_x4(Ah[0], Ah[1], Ah[2], Ah[3], ah + aoff);
            #pragma unroll
            for (int nt = 0; nt < 6; nt++) {
                float* d = D + nt * 4;
                uint32_t b0 = (nt & 1) ? Bh[(nt >> 1) * 4 + 2] : Bh[(nt >> 1) * 4 + 0];
                uint32_t b1 = (nt & 1) ? Bh[(nt >> 1) * 4 + 3] : Bh[(nt >> 1) * 4 + 1];
                mma16816(d[0], d[1], d[2], d[3], Ah[0], Ah[1], Ah[2], Ah[3], b0, b1);
            }
        }
    };

    // ---- prologue ----
    load_x(0);
    ldg_w(0);
    stage(0);
    __syncthreads();

    // ---- pipeline: 12 stages of K=64 ----
    #pragma unroll 1
    for (int st = 0; st < 12; st++) {
        if (st + 1 < 12) ldg_w(st + 1);              // consumed by stage(st+1) below
        if (st == 3) load_x(1);                      // first consumer: stage(4) this iter
        if (st == 7) load_x(2);
        compute(st & 1);
        if (st < 11) stage(st + 1);                  // STS to other buffer
        __syncthreads();
    }

    // ---- epilogue ----
    #pragma unroll
    for (int nt = 0; nt < 6; nt++)
        #pragma unroll
        for (int r = 0; r < 4; r++) {
            int grow = base + wid * 16 + (lane >> 2) + ((r >= 2) ? 8 : 0);
            int q    = nt * 8 + (lane & 3) * 2 + (r & 1);
            out[((size_t)grow * POq + q) * POS + pos] = D[nt * 4 + r] + sbias[q];
        }
}

extern "C" void kernel_launch(void* const* d_in, const int* in_sizes, int n_in,
                              void* d_out, int out_size) {
    const float* x    = (const float*)d_in[0];
    const float* w    = (const float*)d_in[1];
    const float* bias = (const float*)d_in[2];
    float* out        = (float*)d_out;
    (void)in_sizes; (void)n_in; (void)out_size;

    cudaFuncSetAttribute(ttn_conv_hmma_kernel,
                         cudaFuncAttributeMaxDynamicSharedMemorySize, SMEM_BYTES);
    ttn_conv_hmma_kernel<<<POS * 2, 128, SMEM_BYTES>>>(x, w, bias, out);
}

// round 14
// speedup vs baseline: 1.8465x; 1.3537x over previous
#include <cuda_runtime.h>
#include <cuda_fp16.h>
#include <cstdint>

#define CIN 3
#define NY  31
#define POS 961
#define POq 48

// ---- smem layout (bytes) ----
#define SBIAS 0          // 48 floats
#define B0    1024       // B tile: 64 k-rows x 128B (48 halves used), swizzled, fp16
#define B1    9216
#define SMEM_BYTES 17408

__device__ __forceinline__ uint32_t smem_u32(const void* p) {
    uint32_t a;
    asm("{ .reg .u64 t; cvta.to.shared.u64 t, %1; cvt.u32.u64 %0, t; }" : "=r"(a) : "l"(p));
    return a;
}
__device__ __forceinline__ void ldsm_x4t(uint32_t& r0, uint32_t& r1, uint32_t& r2, uint32_t& r3,
                                         uint32_t a) {
    asm volatile("ldmatrix.sync.aligned.m8n8.x4.trans.shared.b16 {%0,%1,%2,%3}, [%4];"
                 : "=r"(r0), "=r"(r1), "=r"(r2), "=r"(r3) : "r"(a));
}
__device__ __forceinline__ void mma16816(float& d0, float& d1, float& d2, float& d3,
                                         uint32_t a0, uint32_t a1, uint32_t a2, uint32_t a3,
                                         uint32_t b0, uint32_t b1) {
    asm volatile("mma.sync.aligned.m16n8k16.row.col.f32.f16.f16.f32 "
                 "{%0,%1,%2,%3}, {%4,%5,%6,%7}, {%8,%9}, {%0,%1,%2,%3};"
                 : "+f"(d0), "+f"(d1), "+f"(d2), "+f"(d3)
                 : "r"(a0), "r"(a1), "r"(a2), "r"(a3), "r"(b0), "r"(b1));
}
__device__ __forceinline__ uint32_t pack_hi(float v0, float v1) {
    __half h0 = __float2half_rn(v0), h1 = __float2half_rn(v1);
    return (uint32_t)__half_as_ushort(h0) | ((uint32_t)__half_as_ushort(h1) << 16);
}
__device__ __forceinline__ void sts32(uint32_t a, uint32_t v) {
    asm volatile("st.shared.b32 [%0], %1;" :: "r"(a), "r"(v) : "memory");
}

extern __shared__ char smem[];

__global__ void __launch_bounds__(128, 5)
ttn_conv_hmma_kernel(const float* __restrict__ x,
                     const float* __restrict__ w,
                     const float* __restrict__ bias,
                     float* __restrict__ out)
{
    const int pos   = blockIdx.x >> 1;     // position; 2 CTAs per position
    const int mhalf = blockIdx.x & 1;      // which 64-row half of M=128
    const int xx    = pos / NY;
    const int yy    = pos - xx * NY;
    const int tid   = threadIdx.x;
    const int lane  = tid & 31;
    const int wid   = tid >> 5;
    const int base  = mhalf * 64;
    const uint32_t sb = smem_u32(smem);
    float* sbias = (float*)(smem + SBIAS);

    if (tid < POq) {
        int p = tid / 6, o = tid - p * 6;
        sbias[tid] = bias[((p * 31 + xx) * 31 + yy) * 6 + o];
    }

    const int bp  = tid >> 4;     // p block (0..7) for weight loads
    const int t16 = tid & 15;

    float D[24];
    #pragma unroll
    for (int i = 0; i < 24; i++) D[i] = 0.f;

    // ---- A is register-resident: this thread's MMA-fragment rows ----
    const int row1 = base + wid * 16 + (lane >> 2);   // global sample row
    const int row2 = row1 + 8;
    // lane's fixed kl set: {kl0, kl0+1, kl0+8, kl0+9}, kl0 = 2*(lane&3)
    const int cq = (lane & 3) >> 1;    // cv indices cq, cq+2
    const int dr = (lane & 1) * 2;     // dv indices dr, dr+1
    float av1[4], bv1[4], cd41[4];
    float av2[4], bv2[4], cd42[4];

    auto load_x = [&](int c) {
        const float* xp1 = x + ((size_t)row1 * CIN + c) * 4096 + xx * 32 + yy;
        const float* xp2 = x + ((size_t)row2 * CIN + c) * 4096 + xx * 32 + yy;
        #pragma unroll
        for (int i = 0; i < 4; i++) {
            av1[i] = xp1[i * 1024];          av2[i] = xp2[i * 1024];
            bv1[i] = xp1[i * 1024 + 32];     bv2[i] = xp2[i * 1024 + 32];
        }
        float c0a = xp1[cq * 1024 + 1],       c1a = xp1[(cq + 2) * 1024 + 1];
        float d0a = xp1[dr * 1024 + 33],      d1a = xp1[(dr + 1) * 1024 + 33];
        cd41[0] = c0a * d0a; cd41[1] = c0a * d1a; cd41[2] = c1a * d0a; cd41[3] = c1a * d1a;
        float c0b = xp2[cq * 1024 + 1],       c1b = xp2[(cq + 2) * 1024 + 1];
        float d0b = xp2[dr * 1024 + 33],      d1b = xp2[(dr + 1) * 1024 + 33];
        cd42[0] = c0b * d0b; cd42[1] = c0b * d1b; cd42[2] = c1b * d0b; cd42[3] = c1b * d1b;
    };

    float4 fb[6];                 // weight prefetch (384 floats / 16 thr / p-block)
    auto ldg_w = [&](int st) {    // stage st (0..11) covers 384 floats per p-block
        int c = st >> 2;
        const float* gw = w + ((size_t)(c * 8 + bp) * POS + pos) * 1536 + (st & 3) * 384;
        #pragma unroll
        for (int r = 0; r < 6; r++) fb[r] = ((const float4*)gw)[t16 + 16 * r];
    };
    auto stageB = [&](int par) {  // write fp16 B tile to buffer `par` (R13 path)
        const uint32_t bh = sb + (par ? B1 : B0);
        #pragma unroll
        for (int r = 0; r < 6; r++) {
            const float* fp = &fb[r].x;
            #pragma unroll
            for (int up = 0; up < 2; up++) {
                int e0 = t16 * 4 + up * 2 + r * 64;   // even; e0%6 in {0,2,4} -> same-k pair
                int k  = e0 / 6, o = e0 - 6 * k;      // k 0..63
                uint32_t n   = (uint32_t)(bp * 6 + o);
                uint32_t off = (uint32_t)k * 128u + 16u * ((n >> 3) ^ ((uint32_t)k & 7u))
                             + (n & 7u) * 2u;
                sts32(bh + off, pack_hi(fp[up * 2], fp[up * 2 + 1]));
            }
        }
    };

    // ---- prologue ----
    load_x(0);
    ldg_w(0);
    stageB(0);
    __syncthreads();

    // ---- pipeline: c (dynamic) x sl (static) = 12 stages of K=64 ----
    #pragma unroll 1
    for (int c = 0; c < CIN; c++) {
        if (c) load_x(c);
        #pragma unroll
        for (int sl = 0; sl < 4; sl++) {
            const int st = c * 4 + sl;
            if (st + 1 < 12) ldg_w(st + 1);

            // ---- compute stage st from B[sl&1] + register A ----
            {
                const uint32_t bh = sb + ((sl & 1) ? B1 : B0);
                #pragma unroll
                for (int s16 = 0; s16 < 4; s16++) {
                    uint32_t Bh[12];
                    uint32_t krow = (uint32_t)(s16 * 16 + ((lane >> 3) & 1) * 8 + (lane & 7));
                    #pragma unroll
                    for (int ntp = 0; ntp < 3; ntp++) {
                        uint32_t n    = (uint32_t)((ntp * 2 + (lane >> 4)) * 8);
                        uint32_t boff = krow * 128u + 16u * ((n >> 3) ^ (krow & 7u));
                        ldsm_x4t(Bh[ntp * 4], Bh[ntp * 4 + 1],
                                 Bh[ntp * 4 + 2], Bh[ntp * 4 + 3], bh + boff);
                    }
                    // A fragment from registers: ij = sl*4 + s16 -> i = sl, j = s16
                    const float ab1 = av1[sl] * bv1[s16];
                    const float ab2 = av2[sl] * bv2[s16];
                    uint32_t Ah0 = pack_hi(ab1 * cd41[0], ab1 * cd41[1]);
                    uint32_t Ah1 = pack_hi(ab2 * cd42[0], ab2 * cd42[1]);
                    uint32_t Ah2 = pack_hi(ab1 * cd41[2], ab1 * cd41[3]);
                    uint32_t Ah3 = pack_hi(ab2 * cd42[2], ab2 * cd42[3]);
                    #pragma unroll
                    for (int nt = 0; nt < 6; nt++) {
                        float* d = D + nt * 4;
                        uint32_t b0 = (nt & 1) ? Bh[(nt >> 1) * 4 + 2] : Bh[(nt >> 1) * 4 + 0];
                        uint32_t b1 = (nt & 1) ? Bh[(nt >> 1) * 4 + 3] : Bh[(nt >> 1) * 4 + 1];
                        mma16816(d[0], d[1], d[2], d[3], Ah0, Ah1, Ah2, Ah3, b0, b1);
                    }
                }
            }

            if (st + 1 < 12) stageB((sl + 1) & 1);   // stage next B tile (other buffer)
            __syncthreads();
        }
    }

    // ---- epilogue ----
    #pragma unroll
    for (int nt = 0; nt < 6; nt++)
        #pragma unroll
        for (int r = 0; r < 4; r++) {
            int grow = base + wid * 16 + (lane >> 2) + ((r >= 2) ? 8 : 0);
            int q    = nt * 8 + (lane & 3) * 2 + (r & 1);
            out[((size_t)grow * POq + q) * POS + pos] = D[nt * 4 + r] + sbias[q];
        }
}

extern "C" void kernel_launch(void* const* d_in, const int* in_sizes, int n_in,
                              void* d_out, int out_size) {
    const float* x    = (const float*)d_in[0];
    const float* w    = (const float*)d_in[1];
    const float* bias = (const float*)d_in[2];
    float* out        = (float*)d_out;
    (void)in_sizes; (void)n_in; (void)out_size;

    cudaFuncSetAttribute(ttn_conv_hmma_kernel,
                         cudaFuncAttributeMaxDynamicSharedMemorySize, SMEM_BYTES);
    ttn_conv_hmma_kernel<<<POS * 2, 128, SMEM_BYTES>>>(x, w, bias, out);
}